// round 5
// baseline (speedup 1.0000x reference)
#include <cuda_runtime.h>
#include <cuda_fp16.h>
#include <cstdint>

// ---------------- problem constants ----------------
#define BROWS 4096
#define NOUT  4096
#define KTOT  4122
#define KPAD  4160            // 130 * 32

#define OFF_CD4 262
#define OFF_CD3 524
#define OFF_CD2 1042
#define OFF_CD1 2071

// ---------------- scratch (device globals; no allocs allowed) ----------------
__device__ float  g_cA1[(size_t)BROWS * 2051];
__device__ float  g_cA2[(size_t)BROWS * 1029];
__device__ float  g_cA3[(size_t)BROWS * 518];
__device__ __half g_C[(size_t)BROWS * KPAD];   // coeffs [M, K] row-major fp16
__device__ __half g_B[(size_t)KPAD * NOUT];    // stacked bases [K, N] row-major fp16

__constant__ float c_lo[8] = {
    -0.010597401784997278f,  0.032883011666982945f,  0.030841381835986965f,
    -0.18703481171888114f,  -0.02798376941698385f,   0.6308807679295904f,
     0.7148465705525415f,    0.23037781330885523f };
__constant__ float c_hi[8] = {
    -0.23037781330885523f,   0.7148465705525415f,   -0.6308807679295904f,
    -0.02798376941698385f,   0.18703481171888114f,   0.030841381835986965f,
    -0.032883011666982945f, -0.010597401784997278f };

// ---------------- DWT: one level, db4, pywt 'symmetric' ----------------
__global__ void dwt_level_kernel(const float* __restrict__ in, int Nin, int Nout,
                                 float* __restrict__ cA_f32,
                                 __half* __restrict__ C,
                                 int cA_col, int cD_col)
{
    int j   = blockIdx.x * blockDim.x + threadIdx.x;
    int row = blockIdx.y;
    if (j >= Nout) return;

    const float* a = in + (size_t)row * Nin;
    float sLo = 0.f, sHi = 0.f;
#pragma unroll
    for (int m = 0; m < 8; m++) {
        int i = 8 + 2 * j - m;
        int idx;
        if (i < 7)            idx = 6 - i;
        else if (i < Nin + 7) idx = i - 7;
        else                  idx = 2 * Nin + 6 - i;
        float v = __ldg(a + idx);
        sLo = fmaf(c_lo[m], v, sLo);
        sHi = fmaf(c_hi[m], v, sHi);
    }
    if (cA_f32)      cA_f32[(size_t)row * Nout + j] = sLo;
    if (cA_col >= 0) C[(size_t)row * KPAD + cA_col + j] = __float2half_rn(sLo);
    C[(size_t)row * KPAD + cD_col + j] = __float2half_rn(sHi);
}

// zero padding columns of C (cols KTOT..KPAD)
__global__ void zero_pad_kernel(__half* __restrict__ C)
{
    int row = blockIdx.x * blockDim.x + threadIdx.x;
    if (row >= BROWS) return;
    for (int c = KTOT; c < KPAD; c++)
        C[(size_t)row * KPAD + c] = __float2half_rn(0.f);
}

// ---------------- pack bases -> fp16 stacked [KPAD, 4096] row-major ----------------
__global__ void pack_b_kernel(const float* __restrict__ b0, const float* __restrict__ b1,
                              const float* __restrict__ b2, const float* __restrict__ b3,
                              const float* __restrict__ b4, __half* __restrict__ Bh)
{
    int n = (blockIdx.x * blockDim.x + threadIdx.x) * 8;
    int k = blockIdx.y;
    if (n >= NOUT) return;

    const float* src = nullptr; int r = 0;
    if      (k < OFF_CD4) { src = b0; r = k; }
    else if (k < OFF_CD3) { src = b1; r = k - OFF_CD4; }
    else if (k < OFF_CD2) { src = b2; r = k - OFF_CD3; }
    else if (k < OFF_CD1) { src = b3; r = k - OFF_CD2; }
    else if (k < KTOT)    { src = b4; r = k - OFF_CD1; }

    __half2 h[4];
    if (src) {
        const float4* p = (const float4*)(src + (size_t)r * NOUT + n);
        float4 v0 = p[0], v1 = p[1];
        h[0] = __floats2half2_rn(v0.x, v0.y);
        h[1] = __floats2half2_rn(v0.z, v0.w);
        h[2] = __floats2half2_rn(v1.x, v1.y);
        h[3] = __floats2half2_rn(v1.z, v1.w);
    } else {
        h[0] = h[1] = h[2] = h[3] = __half2half2(__float2half_rn(0.f));
    }
    *(int4*)(Bh + (size_t)k * NOUT + n) = *(int4*)h;
}

// ---------------- GEMM: [4096,4160] x [4160,4096] fp16 -> fp32 ----------------
// mma.sync.m16n8k16 + ldmatrix + 4-stage cp.async.
// CTA tile 128x256, BK=32, 256 threads, 8 warps as 2(m) x 4(n), warp tile 64x64.
#define BM 128
#define BN 256
#define BK 32
#define STAGES 4
#define A_STAGE_BYTES 8192       // 128 x 32 halves
#define B_STAGE_BYTES 16384      // 32 x 256 halves
#define STAGE_BYTES   24576
#define SMEM_BYTES    (STAGES * STAGE_BYTES)   // 98304

// A smem swizzle: rows paired into 128B lines; chunkIdx = (r&1)*4 + (c>>3)
__device__ __forceinline__ uint32_t aswz(int r, int chunk) {
    return (uint32_t)(((r >> 1) * 128) + ((((r & 1) * 4 + chunk) ^ ((r >> 1) & 7)) << 4));
}
// B smem: 512B rows (32 chunks of 16B); xor low-3 chunk bits by row
__device__ __forceinline__ uint32_t bswz(int r, int chunk) {
    return (uint32_t)(r * 512 + (((chunk & 24) | ((chunk ^ r) & 7)) << 4));
}

__device__ __forceinline__ void cp16(uint32_t saddr, const void* gaddr) {
    asm volatile("cp.async.cg.shared.global [%0], [%1], 16;\n" :: "r"(saddr), "l"(gaddr));
}
__device__ __forceinline__ void ldsm4(uint32_t* r, uint32_t addr) {
    asm volatile("ldmatrix.sync.aligned.m8n8.x4.shared.b16 {%0,%1,%2,%3}, [%4];"
                 : "=r"(r[0]), "=r"(r[1]), "=r"(r[2]), "=r"(r[3]) : "r"(addr));
}
__device__ __forceinline__ void ldsm4t(uint32_t* r, uint32_t addr) {
    asm volatile("ldmatrix.sync.aligned.m8n8.x4.trans.shared.b16 {%0,%1,%2,%3}, [%4];"
                 : "=r"(r[0]), "=r"(r[1]), "=r"(r[2]), "=r"(r[3]) : "r"(addr));
}
__device__ __forceinline__ void mma16816(float* c, const uint32_t* a, uint32_t b0, uint32_t b1) {
    asm volatile("mma.sync.aligned.m16n8k16.row.col.f32.f16.f16.f32 "
                 "{%0,%1,%2,%3}, {%4,%5,%6,%7}, {%8,%9}, {%0,%1,%2,%3};"
                 : "+f"(c[0]), "+f"(c[1]), "+f"(c[2]), "+f"(c[3])
                 : "r"(a[0]), "r"(a[1]), "r"(a[2]), "r"(a[3]), "r"(b0), "r"(b1));
}

__global__ void __launch_bounds__(256, 1)
gemm_kernel(const __half* __restrict__ A, const __half* __restrict__ Bm,
            float* __restrict__ Cout)
{
    constexpr int K = KPAD, N = NOUT;
    extern __shared__ char smem[];
    const uint32_t sbase = (uint32_t)__cvta_generic_to_shared(smem);

    const int tid = threadIdx.x;
    const int wid = tid >> 5, lid = tid & 31;
    const int wm  = wid & 1;        // 0..1 -> 64-row slice
    const int wn  = wid >> 1;       // 0..3 -> 64-col slice
    const int rowBase = blockIdx.y * BM;
    const int colBase = blockIdx.x * BN;

    const int l15 = lid & 15, lc = lid >> 4;

    // ---- loader geometry ----
    // A: 512 int4/stage -> 2 per thread
    const int aR0 = (tid + 0)   >> 2, aC0 = (tid + 0)   & 3;
    const int aR1 = (tid + 256) >> 2, aC1 = (tid + 256) & 3;
    const uint32_t aS0 = aswz(aR0, aC0), aS1 = aswz(aR1, aC1);
    // B: 1024 int4/stage -> 4 per thread (rows 0..31, 32 chunks/row)
    int bR[4], bC[4]; uint32_t bS[4];
#pragma unroll
    for (int i = 0; i < 4; i++) {
        const int idx = i * 256 + tid;
        bR[i] = idx >> 5; bC[i] = idx & 31;
        bS[i] = bswz(bR[i], bC[i]);
    }

    const __half* Ag = A + (size_t)rowBase * K;
    const __half* Bg = Bm + colBase;

    // ---- ldmatrix relative offsets ----
    uint32_t relA[4][2];
#pragma unroll
    for (int i = 0; i < 4; i++) {
        const int r   = wm * 64 + i * 16 + l15;
        const int bse = (r >> 1) * 128, key = (r & 1) * 4, x = (r >> 1) & 7;
#pragma unroll
        for (int ks = 0; ks < 2; ks++)
            relA[i][ks] = (uint32_t)(bse + (((key + ks * 2 + lc) ^ x) << 4));
    }
    uint32_t relB[4][2];
#pragma unroll
    for (int g = 0; g < 4; g++) {
        const int chunk = wn * 8 + g * 2 + lc;
#pragma unroll
        for (int ks = 0; ks < 2; ks++) {
            const int r = ks * 16 + l15;
            relB[g][ks] = (uint32_t)(r * 512 + (((chunk & 24) | ((chunk ^ r) & 7)) << 4));
        }
    }

    auto issue_stage = [&](int t) {
        const int kb = t * BK;
        const uint32_t sa = sbase + (t & (STAGES - 1)) * STAGE_BYTES;
        const uint32_t sb = sa + A_STAGE_BYTES;
        cp16(sa + aS0, Ag + (size_t)aR0 * K + kb + aC0 * 8);
        cp16(sa + aS1, Ag + (size_t)aR1 * K + kb + aC1 * 8);
#pragma unroll
        for (int i = 0; i < 4; i++)
            cp16(sb + bS[i], Bg + (size_t)(kb + bR[i]) * N + bC[i] * 8);
        asm volatile("cp.async.commit_group;\n" ::: "memory");
    };

    float acc[4][8][4];
#pragma unroll
    for (int i = 0; i < 4; i++)
#pragma unroll
        for (int j = 0; j < 8; j++)
#pragma unroll
            for (int q = 0; q < 4; q++) acc[i][j][q] = 0.f;

    constexpr int NT = K / BK;    // 130
    issue_stage(0); issue_stage(1); issue_stage(2);

    for (int t = 0; t < NT; t++) {
        asm volatile("cp.async.wait_group 2;\n" ::: "memory");
        __syncthreads();
        if (t + 3 < NT) issue_stage(t + 3);

        const uint32_t sa = sbase + (t & (STAGES - 1)) * STAGE_BYTES;
        const uint32_t sb = sa + A_STAGE_BYTES;

#pragma unroll
        for (int ks = 0; ks < 2; ks++) {
            uint32_t af[4][4], bf[4][4];
#pragma unroll
            for (int i = 0; i < 4; i++) ldsm4(af[i], sa + relA[i][ks]);
#pragma unroll
            for (int g = 0; g < 4; g++) ldsm4t(bf[g], sb + relB[g][ks]);
#pragma unroll
            for (int i = 0; i < 4; i++)
#pragma unroll
                for (int j = 0; j < 8; j++)
                    mma16816(acc[i][j], af[i], bf[j >> 1][(j & 1) * 2],
                             bf[j >> 1][(j & 1) * 2 + 1]);
        }
    }

    // ---- epilogue: fragment -> gmem (float2 stores) ----
    const int er = lid >> 2, ec = (lid & 3) * 2;
#pragma unroll
    for (int i = 0; i < 4; i++) {
        const int row0 = rowBase + wm * 64 + i * 16 + er;
#pragma unroll
        for (int j = 0; j < 8; j++) {
            const int col = colBase + wn * 64 + j * 8 + ec;
            float* p0 = Cout + (size_t)row0 * N + col;
            float* p1 = Cout + (size_t)(row0 + 8) * N + col;
            p0[0] = acc[i][j][0]; p0[1] = acc[i][j][1];
            p1[0] = acc[i][j][2]; p1[1] = acc[i][j][3];
        }
    }
}

// ---------------- launch ----------------
extern "C" void kernel_launch(void* const* d_in, const int* in_sizes, int n_in,
                              void* d_out, int out_size)
{
    const float* x  = (const float*)d_in[0];
    const float* b0 = (const float*)d_in[1];
    const float* b1 = (const float*)d_in[2];
    const float* b2 = (const float*)d_in[3];
    const float* b3 = (const float*)d_in[4];
    const float* b4 = (const float*)d_in[5];
    float* out = (float*)d_out;

    float  *cA1, *cA2, *cA3;
    __half *Cm, *Bm;
    cudaGetSymbolAddress((void**)&cA1, g_cA1);
    cudaGetSymbolAddress((void**)&cA2, g_cA2);
    cudaGetSymbolAddress((void**)&cA3, g_cA3);
    cudaGetSymbolAddress((void**)&Cm,  g_C);
    cudaGetSymbolAddress((void**)&Bm,  g_B);

    cudaFuncSetAttribute(gemm_kernel,
                         cudaFuncAttributeMaxDynamicSharedMemorySize, SMEM_BYTES);

    // 4 DWT levels: 4096 -> 2051 -> 1029 -> 518 -> 262
    dwt_level_kernel<<<dim3((2051 + 255) / 256, BROWS), 256>>>(x,   4096, 2051, cA1, Cm, -1, OFF_CD1);
    dwt_level_kernel<<<dim3((1029 + 255) / 256, BROWS), 256>>>(cA1, 2051, 1029, cA2, Cm, -1, OFF_CD2);
    dwt_level_kernel<<<dim3(( 518 + 255) / 256, BROWS), 256>>>(cA2, 1029,  518, cA3, Cm, -1, OFF_CD3);
    dwt_level_kernel<<<dim3(( 262 + 255) / 256, BROWS), 256>>>(cA3,  518,  262, nullptr, Cm, 0, OFF_CD4);

    zero_pad_kernel<<<(BROWS + 255) / 256, 256>>>(Cm);
    pack_b_kernel<<<dim3(NOUT / (256 * 8), KPAD), 256>>>(b0, b1, b2, b3, b4, Bm);

    gemm_kernel<<<dim3(NOUT / BN, BROWS / BM), 256, SMEM_BYTES>>>(Cm, Bm, out);
}

// round 6
// speedup vs baseline: 1.2239x; 1.2239x over previous
#include <cuda_runtime.h>
#include <cuda_fp16.h>
#include <cstdint>

// ---------------- problem constants ----------------
#define BROWS 4096
#define NOUT  4096
#define KTOT  4122
#define KPAD  4160            // 130 * 32

#define OFF_CD4 262
#define OFF_CD3 524
#define OFF_CD2 1042
#define OFF_CD1 2071

// ---------------- scratch (device globals; no allocs allowed) ----------------
__device__ float  g_cA1[(size_t)BROWS * 2051];
__device__ float  g_cA2[(size_t)BROWS * 1029];
__device__ float  g_cA3[(size_t)BROWS * 518];
__device__ __half g_C[(size_t)BROWS * KPAD];   // coeffs [M, K] row-major fp16
__device__ __half g_B[(size_t)KPAD * NOUT];    // stacked bases [K, N] row-major fp16

__constant__ float c_lo[8] = {
    -0.010597401784997278f,  0.032883011666982945f,  0.030841381835986965f,
    -0.18703481171888114f,  -0.02798376941698385f,   0.6308807679295904f,
     0.7148465705525415f,    0.23037781330885523f };
__constant__ float c_hi[8] = {
    -0.23037781330885523f,   0.7148465705525415f,   -0.6308807679295904f,
    -0.02798376941698385f,   0.18703481171888114f,   0.030841381835986965f,
    -0.032883011666982945f, -0.010597401784997278f };

// ---------------- DWT: one level, db4, pywt 'symmetric' ----------------
__global__ void dwt_level_kernel(const float* __restrict__ in, int Nin, int Nout,
                                 float* __restrict__ cA_f32,
                                 __half* __restrict__ C,
                                 int cA_col, int cD_col)
{
    int j   = blockIdx.x * blockDim.x + threadIdx.x;
    int row = blockIdx.y;
    if (j >= Nout) return;

    const float* a = in + (size_t)row * Nin;
    float sLo = 0.f, sHi = 0.f;
#pragma unroll
    for (int m = 0; m < 8; m++) {
        int i = 8 + 2 * j - m;
        int idx;
        if (i < 7)            idx = 6 - i;
        else if (i < Nin + 7) idx = i - 7;
        else                  idx = 2 * Nin + 6 - i;
        float v = __ldg(a + idx);
        sLo = fmaf(c_lo[m], v, sLo);
        sHi = fmaf(c_hi[m], v, sHi);
    }
    if (cA_f32)      cA_f32[(size_t)row * Nout + j] = sLo;
    if (cA_col >= 0) C[(size_t)row * KPAD + cA_col + j] = __float2half_rn(sLo);
    C[(size_t)row * KPAD + cD_col + j] = __float2half_rn(sHi);
}

// zero padding columns of C (cols KTOT..KPAD)
__global__ void zero_pad_kernel(__half* __restrict__ C)
{
    int row = blockIdx.x * blockDim.x + threadIdx.x;
    if (row >= BROWS) return;
    for (int c = KTOT; c < KPAD; c++)
        C[(size_t)row * KPAD + c] = __float2half_rn(0.f);
}

// ---------------- pack bases -> fp16 stacked [KPAD, 4096] row-major ----------------
__global__ void pack_b_kernel(const float* __restrict__ b0, const float* __restrict__ b1,
                              const float* __restrict__ b2, const float* __restrict__ b3,
                              const float* __restrict__ b4, __half* __restrict__ Bh)
{
    int n = (blockIdx.x * blockDim.x + threadIdx.x) * 8;
    int k = blockIdx.y;
    if (n >= NOUT) return;

    const float* src = nullptr; int r = 0;
    if      (k < OFF_CD4) { src = b0; r = k; }
    else if (k < OFF_CD3) { src = b1; r = k - OFF_CD4; }
    else if (k < OFF_CD2) { src = b2; r = k - OFF_CD3; }
    else if (k < OFF_CD1) { src = b3; r = k - OFF_CD2; }
    else if (k < KTOT)    { src = b4; r = k - OFF_CD1; }

    __half2 h[4];
    if (src) {
        const float4* p = (const float4*)(src + (size_t)r * NOUT + n);
        float4 v0 = p[0], v1 = p[1];
        h[0] = __floats2half2_rn(v0.x, v0.y);
        h[1] = __floats2half2_rn(v0.z, v0.w);
        h[2] = __floats2half2_rn(v1.x, v1.y);
        h[3] = __floats2half2_rn(v1.z, v1.w);
    } else {
        h[0] = h[1] = h[2] = h[3] = __half2half2(__float2half_rn(0.f));
    }
    *(int4*)(Bh + (size_t)k * NOUT + n) = *(int4*)h;
}

// ---------------- GEMM: [4096,4160] x [4160,4096] fp16 -> fp32 ----------------
// mma.sync.m16n8k16 + ldmatrix + 3-stage cp.async, 2 CTAs/SM.
// CTA tile 128x128, BK=32, 256 threads, 8 warps as 2(m) x 4(n), warp tile 64x32.
#define BM 128
#define BN 128
#define BK 32
#define STAGES 3
#define A_STAGE_BYTES 8192      // 128 x 32 halves
#define B_STAGE_BYTES 8192      // 32 x 128 halves
#define STAGE_BYTES   16384
#define SMEM_BYTES    (STAGES * STAGE_BYTES)   // 49152

// A smem swizzle: rows paired into 128B lines; chunkIdx = (r&1)*4 + (c>>3)
__device__ __forceinline__ uint32_t aswz(int r, int chunk) {
    return (uint32_t)(((r >> 1) * 128) + ((((r & 1) * 4 + chunk) ^ ((r >> 1) & 7)) << 4));
}
// B smem: 256B rows, xor low-3 chunk bits by row
__device__ __forceinline__ uint32_t bswz(int r, int chunk) {
    return (uint32_t)(r * 256 + (((chunk & 8) | ((chunk ^ r) & 7)) << 4));
}

__device__ __forceinline__ void cp16(uint32_t saddr, const void* gaddr) {
    asm volatile("cp.async.cg.shared.global [%0], [%1], 16;\n" :: "r"(saddr), "l"(gaddr));
}
__device__ __forceinline__ void ldsm4(uint32_t* r, uint32_t addr) {
    asm volatile("ldmatrix.sync.aligned.m8n8.x4.shared.b16 {%0,%1,%2,%3}, [%4];"
                 : "=r"(r[0]), "=r"(r[1]), "=r"(r[2]), "=r"(r[3]) : "r"(addr));
}
__device__ __forceinline__ void ldsm4t(uint32_t* r, uint32_t addr) {
    asm volatile("ldmatrix.sync.aligned.m8n8.x4.trans.shared.b16 {%0,%1,%2,%3}, [%4];"
                 : "=r"(r[0]), "=r"(r[1]), "=r"(r[2]), "=r"(r[3]) : "r"(addr));
}
__device__ __forceinline__ void mma16816(float* c, const uint32_t* a, uint32_t b0, uint32_t b1) {
    asm volatile("mma.sync.aligned.m16n8k16.row.col.f32.f16.f16.f32 "
                 "{%0,%1,%2,%3}, {%4,%5,%6,%7}, {%8,%9}, {%0,%1,%2,%3};"
                 : "+f"(c[0]), "+f"(c[1]), "+f"(c[2]), "+f"(c[3])
                 : "r"(a[0]), "r"(a[1]), "r"(a[2]), "r"(a[3]), "r"(b0), "r"(b1));
}

__global__ void __launch_bounds__(256, 2)
gemm_kernel(const __half* __restrict__ A, const __half* __restrict__ Bm,
            float* __restrict__ Cout)
{
    constexpr int K = KPAD, N = NOUT;
    extern __shared__ char smem[];
    const uint32_t sbase = (uint32_t)__cvta_generic_to_shared(smem);

    const int tid = threadIdx.x;
    const int wid = tid >> 5, lid = tid & 31;
    const int wm  = wid & 1;        // 0..1 -> 64-row slice
    const int wn  = wid >> 1;       // 0..3 -> 32-col slice
    const int rowBase = blockIdx.y * BM;
    const int colBase = blockIdx.x * BN;

    const int l15 = lid & 15, lc = lid >> 4;

    // ---- loader geometry ----
    const int aR0 = (tid + 0)   >> 2, aC0 = (tid + 0)   & 3;
    const int aR1 = (tid + 256) >> 2, aC1 = (tid + 256) & 3;
    const uint32_t aS0 = aswz(aR0, aC0), aS1 = aswz(aR1, aC1);
    const int bR0 = (tid + 0)   >> 4, bC0 = (tid + 0)   & 15;
    const int bR1 = (tid + 256) >> 4, bC1 = (tid + 256) & 15;
    const uint32_t bS0 = bswz(bR0, bC0), bS1 = bswz(bR1, bC1);

    const __half* Ag = A + (size_t)rowBase * K;
    const __half* Bg = Bm + colBase;

    // ---- ldmatrix relative offsets ----
    uint32_t relA[4][2];
#pragma unroll
    for (int i = 0; i < 4; i++) {
        const int r   = wm * 64 + i * 16 + l15;
        const int bse = (r >> 1) * 128, key = (r & 1) * 4, x = (r >> 1) & 7;
#pragma unroll
        for (int ks = 0; ks < 2; ks++)
            relA[i][ks] = (uint32_t)(bse + (((key + ks * 2 + lc) ^ x) << 4));
    }
    uint32_t relB[2][2];
#pragma unroll
    for (int g = 0; g < 2; g++) {
        const int chunk = wn * 4 + g * 2 + lc;
#pragma unroll
        for (int ks = 0; ks < 2; ks++) {
            const int r = ks * 16 + l15;
            relB[g][ks] = (uint32_t)(r * 256 + (((chunk & 8) | ((chunk ^ r) & 7)) << 4));
        }
    }

    auto issue_stage = [&](int t, int slot) {
        const int kb = t * BK;
        const uint32_t sa = sbase + slot * STAGE_BYTES;
        const uint32_t sb = sa + A_STAGE_BYTES;
        cp16(sa + aS0, Ag + (size_t)aR0 * K + kb + aC0 * 8);
        cp16(sa + aS1, Ag + (size_t)aR1 * K + kb + aC1 * 8);
        cp16(sb + bS0, Bg + (size_t)(kb + bR0) * N + bC0 * 8);
        cp16(sb + bS1, Bg + (size_t)(kb + bR1) * N + bC1 * 8);
        asm volatile("cp.async.commit_group;\n" ::: "memory");
    };

    float acc[4][4][4];
#pragma unroll
    for (int i = 0; i < 4; i++)
#pragma unroll
        for (int j = 0; j < 4; j++)
#pragma unroll
            for (int q = 0; q < 4; q++) acc[i][j][q] = 0.f;

    constexpr int NT = K / BK;    // 130
    issue_stage(0, 0);
    issue_stage(1, 1);

    int cs = 0, ps = 2;           // compute slot, prefetch slot
    for (int t = 0; t < NT; t++) {
        asm volatile("cp.async.wait_group 1;\n" ::: "memory");
        __syncthreads();
        if (t + 2 < NT) issue_stage(t + 2, ps);

        const uint32_t sa = sbase + cs * STAGE_BYTES;
        const uint32_t sb = sa + A_STAGE_BYTES;

#pragma unroll
        for (int ks = 0; ks < 2; ks++) {
            uint32_t af[4][4], bf[2][4];
#pragma unroll
            for (int i = 0; i < 4; i++) ldsm4(af[i], sa + relA[i][ks]);
#pragma unroll
            for (int g = 0; g < 2; g++) ldsm4t(bf[g], sb + relB[g][ks]);
#pragma unroll
            for (int i = 0; i < 4; i++)
#pragma unroll
                for (int j = 0; j < 4; j++)
                    mma16816(acc[i][j], af[i], bf[j >> 1][(j & 1) * 2],
                             bf[j >> 1][(j & 1) * 2 + 1]);
        }
        cs = (cs == STAGES - 1) ? 0 : cs + 1;
        ps = (ps == STAGES - 1) ? 0 : ps + 1;
    }

    // ---- epilogue: fragment -> gmem (float2 stores) ----
    const int er = lid >> 2, ec = (lid & 3) * 2;
#pragma unroll
    for (int i = 0; i < 4; i++) {
        const int row0 = rowBase + wm * 64 + i * 16 + er;
#pragma unroll
        for (int j = 0; j < 4; j++) {
            const int col = colBase + wn * 32 + j * 8 + ec;
            float* p0 = Cout + (size_t)row0 * N + col;
            float* p1 = Cout + (size_t)(row0 + 8) * N + col;
            p0[0] = acc[i][j][0]; p0[1] = acc[i][j][1];
            p1[0] = acc[i][j][2]; p1[1] = acc[i][j][3];
        }
    }
}

// ---------------- launch ----------------
extern "C" void kernel_launch(void* const* d_in, const int* in_sizes, int n_in,
                              void* d_out, int out_size)
{
    const float* x  = (const float*)d_in[0];
    const float* b0 = (const float*)d_in[1];
    const float* b1 = (const float*)d_in[2];
    const float* b2 = (const float*)d_in[3];
    const float* b3 = (const float*)d_in[4];
    const float* b4 = (const float*)d_in[5];
    float* out = (float*)d_out;

    float  *cA1, *cA2, *cA3;
    __half *Cm, *Bm;
    cudaGetSymbolAddress((void**)&cA1, g_cA1);
    cudaGetSymbolAddress((void**)&cA2, g_cA2);
    cudaGetSymbolAddress((void**)&cA3, g_cA3);
    cudaGetSymbolAddress((void**)&Cm,  g_C);
    cudaGetSymbolAddress((void**)&Bm,  g_B);

    cudaFuncSetAttribute(gemm_kernel,
                         cudaFuncAttributeMaxDynamicSharedMemorySize, SMEM_BYTES);

    // 4 DWT levels: 4096 -> 2051 -> 1029 -> 518 -> 262
    dwt_level_kernel<<<dim3((2051 + 255) / 256, BROWS), 256>>>(x,   4096, 2051, cA1, Cm, -1, OFF_CD1);
    dwt_level_kernel<<<dim3((1029 + 255) / 256, BROWS), 256>>>(cA1, 2051, 1029, cA2, Cm, -1, OFF_CD2);
    dwt_level_kernel<<<dim3(( 518 + 255) / 256, BROWS), 256>>>(cA2, 1029,  518, cA3, Cm, -1, OFF_CD3);
    dwt_level_kernel<<<dim3(( 262 + 255) / 256, BROWS), 256>>>(cA3,  518,  262, nullptr, Cm, 0, OFF_CD4);

    zero_pad_kernel<<<(BROWS + 255) / 256, 256>>>(Cm);
    pack_b_kernel<<<dim3(NOUT / (256 * 8), KPAD), 256>>>(b0, b1, b2, b3, b4, Bm);

    gemm_kernel<<<dim3(NOUT / BN, BROWS / BM), 256, SMEM_BYTES>>>(Cm, Bm, out);
}

// round 7
// speedup vs baseline: 1.2788x; 1.0449x over previous
#include <cuda_runtime.h>
#include <cuda_fp16.h>
#include <cstdint>

// ---------------- problem constants ----------------
#define BROWS 4096
#define NOUT  4096
#define KTOT  4122
#define KPAD  4160            // 65 * 64

#define OFF_CD4 262
#define OFF_CD3 524
#define OFF_CD2 1042
#define OFF_CD1 2071

// ---------------- scratch (device globals; no allocs allowed) ----------------
__device__ float  g_cA1[(size_t)BROWS * 2051];
__device__ float  g_cA2[(size_t)BROWS * 1029];
__device__ float  g_cA3[(size_t)BROWS * 518];
__device__ __half g_C[(size_t)BROWS * KPAD];   // coeffs [M, K] row-major fp16
__device__ __half g_B[(size_t)KPAD * NOUT];    // stacked bases [K, N] row-major fp16

__constant__ float c_lo[8] = {
    -0.010597401784997278f,  0.032883011666982945f,  0.030841381835986965f,
    -0.18703481171888114f,  -0.02798376941698385f,   0.6308807679295904f,
     0.7148465705525415f,    0.23037781330885523f };
__constant__ float c_hi[8] = {
    -0.23037781330885523f,   0.7148465705525415f,   -0.6308807679295904f,
    -0.02798376941698385f,   0.18703481171888114f,   0.030841381835986965f,
    -0.032883011666982945f, -0.010597401784997278f };

// ---------------- DWT: one level, db4, pywt 'symmetric' ----------------
__global__ void dwt_level_kernel(const float* __restrict__ in, int Nin, int Nout,
                                 float* __restrict__ cA_f32,
                                 __half* __restrict__ C,
                                 int cA_col, int cD_col)
{
    int j   = blockIdx.x * blockDim.x + threadIdx.x;
    int row = blockIdx.y;
    if (j >= Nout) return;

    const float* a = in + (size_t)row * Nin;
    float sLo = 0.f, sHi = 0.f;
#pragma unroll
    for (int m = 0; m < 8; m++) {
        int i = 8 + 2 * j - m;
        int idx;
        if (i < 7)            idx = 6 - i;
        else if (i < Nin + 7) idx = i - 7;
        else                  idx = 2 * Nin + 6 - i;
        float v = __ldg(a + idx);
        sLo = fmaf(c_lo[m], v, sLo);
        sHi = fmaf(c_hi[m], v, sHi);
    }
    if (cA_f32)      cA_f32[(size_t)row * Nout + j] = sLo;
    if (cA_col >= 0) C[(size_t)row * KPAD + cA_col + j] = __float2half_rn(sLo);
    C[(size_t)row * KPAD + cD_col + j] = __float2half_rn(sHi);
}

// zero padding columns of C (cols KTOT..KPAD)
__global__ void zero_pad_kernel(__half* __restrict__ C)
{
    int row = blockIdx.x * blockDim.x + threadIdx.x;
    if (row >= BROWS) return;
    for (int c = KTOT; c < KPAD; c++)
        C[(size_t)row * KPAD + c] = __float2half_rn(0.f);
}

// ---------------- pack bases -> fp16 stacked [KPAD, 4096] row-major ----------------
__global__ void pack_b_kernel(const float* __restrict__ b0, const float* __restrict__ b1,
                              const float* __restrict__ b2, const float* __restrict__ b3,
                              const float* __restrict__ b4, __half* __restrict__ Bh)
{
    int n = (blockIdx.x * blockDim.x + threadIdx.x) * 8;
    int k = blockIdx.y;
    if (n >= NOUT) return;

    const float* src = nullptr; int r = 0;
    if      (k < OFF_CD4) { src = b0; r = k; }
    else if (k < OFF_CD3) { src = b1; r = k - OFF_CD4; }
    else if (k < OFF_CD2) { src = b2; r = k - OFF_CD3; }
    else if (k < OFF_CD1) { src = b3; r = k - OFF_CD2; }
    else if (k < KTOT)    { src = b4; r = k - OFF_CD1; }

    __half2 h[4];
    if (src) {
        const float4* p = (const float4*)(src + (size_t)r * NOUT + n);
        float4 v0 = p[0], v1 = p[1];
        h[0] = __floats2half2_rn(v0.x, v0.y);
        h[1] = __floats2half2_rn(v0.z, v0.w);
        h[2] = __floats2half2_rn(v1.x, v1.y);
        h[3] = __floats2half2_rn(v1.z, v1.w);
    } else {
        h[0] = h[1] = h[2] = h[3] = __half2half2(__float2half_rn(0.f));
    }
    *(int4*)(Bh + (size_t)k * NOUT + n) = *(int4*)h;
}

// ---------------- GEMM: [4096,4160] x [4160,4096] fp16 -> fp32 ----------------
// mma.sync.m16n8k16 + ldmatrix + 3-stage cp.async, BK=64, 2 CTAs/SM.
// CTA tile 128x128, 256 threads, 8 warps as 2(m) x 4(n), warp tile 64x32.
#define BM 128
#define BN 128
#define BK 64
#define STAGES 3
#define A_STAGE_BYTES 16384     // 128 rows x 64 halves (128B rows)
#define B_STAGE_BYTES 16384     // 64 rows x 128 halves (256B rows)
#define STAGE_BYTES   32768
#define SMEM_BYTES    (STAGES * STAGE_BYTES)   // 98304

// A smem: 128B rows, 8 chunks of 16B; chunk ^= (row & 7)
__device__ __forceinline__ uint32_t aswz(int r, int chunk) {
    return (uint32_t)(r * 128 + ((chunk ^ (r & 7)) << 4));
}
// B smem: 256B rows, 16 chunks of 16B; low-3 chunk bits ^= (row & 7)
__device__ __forceinline__ uint32_t bswz(int r, int chunk) {
    return (uint32_t)(r * 256 + (((chunk & 8) | ((chunk ^ r) & 7)) << 4));
}

__device__ __forceinline__ void cp16(uint32_t saddr, const void* gaddr) {
    asm volatile("cp.async.cg.shared.global [%0], [%1], 16;\n" :: "r"(saddr), "l"(gaddr));
}
__device__ __forceinline__ void ldsm4(uint32_t* r, uint32_t addr) {
    asm volatile("ldmatrix.sync.aligned.m8n8.x4.shared.b16 {%0,%1,%2,%3}, [%4];"
                 : "=r"(r[0]), "=r"(r[1]), "=r"(r[2]), "=r"(r[3]) : "r"(addr));
}
__device__ __forceinline__ void ldsm4t(uint32_t* r, uint32_t addr) {
    asm volatile("ldmatrix.sync.aligned.m8n8.x4.trans.shared.b16 {%0,%1,%2,%3}, [%4];"
                 : "=r"(r[0]), "=r"(r[1]), "=r"(r[2]), "=r"(r[3]) : "r"(addr));
}
__device__ __forceinline__ void mma16816(float* c, const uint32_t* a, uint32_t b0, uint32_t b1) {
    asm volatile("mma.sync.aligned.m16n8k16.row.col.f32.f16.f16.f32 "
                 "{%0,%1,%2,%3}, {%4,%5,%6,%7}, {%8,%9}, {%0,%1,%2,%3};"
                 : "+f"(c[0]), "+f"(c[1]), "+f"(c[2]), "+f"(c[3])
                 : "r"(a[0]), "r"(a[1]), "r"(a[2]), "r"(a[3]), "r"(b0), "r"(b1));
}

__global__ void __launch_bounds__(256, 2)
gemm_kernel(const __half* __restrict__ A, const __half* __restrict__ Bm,
            float* __restrict__ Cout)
{
    constexpr int K = KPAD, N = NOUT;
    extern __shared__ char smem[];
    const uint32_t sbase = (uint32_t)__cvta_generic_to_shared(smem);

    const int tid = threadIdx.x;
    const int wid = tid >> 5, lid = tid & 31;
    const int wm  = wid & 1;        // 0..1 -> 64-row slice
    const int wn  = wid >> 1;       // 0..3 -> 32-col slice
    const int rowBase = blockIdx.y * BM;
    const int colBase = blockIdx.x * BN;

    const int l15 = lid & 15, lc = lid >> 4;

    // ---- loader geometry ----
    // A: 1024 int4/stage -> 4 per thread; row = idx>>3, chunk = idx&7
    int aR[4]; uint32_t aS[4];
#pragma unroll
    for (int i = 0; i < 4; i++) {
        const int idx = i * 256 + tid;
        aR[i] = idx >> 3;
        aS[i] = aswz(aR[i], idx & 7);
    }
    // B: 1024 int4/stage -> 4 per thread; row = idx>>4, chunk = idx&15
    int bR[4]; uint32_t bS[4];
#pragma unroll
    for (int i = 0; i < 4; i++) {
        const int idx = i * 256 + tid;
        bR[i] = idx >> 4;
        bS[i] = bswz(bR[i], idx & 15);
    }

    const __half* Ag = A + (size_t)rowBase * K;
    const __half* Bg = Bm + colBase;

    // ---- ldmatrix bases (offsets computed per ks to save registers) ----
    // A row for tile i: r = wm*64 + i*16 + l15 ; addr = r*128 + (((ks*2+lc)^ (r&7))<<4)
    uint32_t aBase[4]; int aX[4];
#pragma unroll
    for (int i = 0; i < 4; i++) {
        const int r = wm * 64 + i * 16 + l15;
        aBase[i] = (uint32_t)(r * 128);
        aX[i] = r & 7;
    }
    // B chunk for group g: chunk = wn*4 + g*2 + lc ; row r = ks*16 + l15
    int bChunk[2] = { wn * 4 + 0 * 2 + lc, wn * 4 + 1 * 2 + lc };

    auto issue_stage = [&](int t, int slot) {
        const int kb = t * BK;
        const uint32_t sa = sbase + slot * STAGE_BYTES;
        const uint32_t sb = sa + A_STAGE_BYTES;
#pragma unroll
        for (int i = 0; i < 4; i++) {
            const int idx = i * 256 + tid;
            cp16(sa + aS[i], Ag + (size_t)aR[i] * K + kb + (idx & 7) * 8);
        }
#pragma unroll
        for (int i = 0; i < 4; i++) {
            const int idx = i * 256 + tid;
            cp16(sb + bS[i], Bg + (size_t)(kb + bR[i]) * N + (idx & 15) * 8);
        }
        asm volatile("cp.async.commit_group;\n" ::: "memory");
    };

    float acc[4][4][4];
#pragma unroll
    for (int i = 0; i < 4; i++)
#pragma unroll
        for (int j = 0; j < 4; j++)
#pragma unroll
            for (int q = 0; q < 4; q++) acc[i][j][q] = 0.f;

    constexpr int NT = K / BK;    // 65
    issue_stage(0, 0);
    issue_stage(1, 1);

    int cs = 0, ps = 2;
    for (int t = 0; t < NT; t++) {
        asm volatile("cp.async.wait_group 1;\n" ::: "memory");
        __syncthreads();
        if (t + 2 < NT) issue_stage(t + 2, ps);

        const uint32_t sa = sbase + cs * STAGE_BYTES;
        const uint32_t sb = sa + A_STAGE_BYTES;

#pragma unroll
        for (int ks = 0; ks < 4; ks++) {
            uint32_t af[4][4], bf[2][4];
#pragma unroll
            for (int i = 0; i < 4; i++)
                ldsm4(af[i], sa + aBase[i] + (uint32_t)((((ks * 2 + lc) ^ aX[i]) << 4)));
#pragma unroll
            for (int g = 0; g < 2; g++) {
                const int r = ks * 16 + l15;
                ldsm4t(bf[g], sb + (uint32_t)(r * 256 +
                        (((bChunk[g] & 8) | ((bChunk[g] ^ r) & 7)) << 4)));
            }
#pragma unroll
            for (int i = 0; i < 4; i++)
#pragma unroll
                for (int j = 0; j < 4; j++)
                    mma16816(acc[i][j], af[i], bf[j >> 1][(j & 1) * 2],
                             bf[j >> 1][(j & 1) * 2 + 1]);
        }
        cs = (cs == STAGES - 1) ? 0 : cs + 1;
        ps = (ps == STAGES - 1) ? 0 : ps + 1;
    }

    // ---- epilogue: fragment -> gmem (float2 stores) ----
    const int er = lid >> 2, ec = (lid & 3) * 2;
#pragma unroll
    for (int i = 0; i < 4; i++) {
        const int row0 = rowBase + wm * 64 + i * 16 + er;
#pragma unroll
        for (int j = 0; j < 4; j++) {
            const int col = colBase + wn * 32 + j * 8 + ec;
            float* p0 = Cout + (size_t)row0 * N + col;
            float* p1 = Cout + (size_t)(row0 + 8) * N + col;
            p0[0] = acc[i][j][0]; p0[1] = acc[i][j][1];
            p1[0] = acc[i][j][2]; p1[1] = acc[i][j][3];
        }
    }
}

// ---------------- launch ----------------
extern "C" void kernel_launch(void* const* d_in, const int* in_sizes, int n_in,
                              void* d_out, int out_size)
{
    const float* x  = (const float*)d_in[0];
    const float* b0 = (const float*)d_in[1];
    const float* b1 = (const float*)d_in[2];
    const float* b2 = (const float*)d_in[3];
    const float* b3 = (const float*)d_in[4];
    const float* b4 = (const float*)d_in[5];
    float* out = (float*)d_out;

    float  *cA1, *cA2, *cA3;
    __half *Cm, *Bm;
    cudaGetSymbolAddress((void**)&cA1, g_cA1);
    cudaGetSymbolAddress((void**)&cA2, g_cA2);
    cudaGetSymbolAddress((void**)&cA3, g_cA3);
    cudaGetSymbolAddress((void**)&Cm,  g_C);
    cudaGetSymbolAddress((void**)&Bm,  g_B);

    cudaFuncSetAttribute(gemm_kernel,
                         cudaFuncAttributeMaxDynamicSharedMemorySize, SMEM_BYTES);

    // 4 DWT levels: 4096 -> 2051 -> 1029 -> 518 -> 262
    dwt_level_kernel<<<dim3((2051 + 255) / 256, BROWS), 256>>>(x,   4096, 2051, cA1, Cm, -1, OFF_CD1);
    dwt_level_kernel<<<dim3((1029 + 255) / 256, BROWS), 256>>>(cA1, 2051, 1029, cA2, Cm, -1, OFF_CD2);
    dwt_level_kernel<<<dim3(( 518 + 255) / 256, BROWS), 256>>>(cA2, 1029,  518, cA3, Cm, -1, OFF_CD3);
    dwt_level_kernel<<<dim3(( 262 + 255) / 256, BROWS), 256>>>(cA3,  518,  262, nullptr, Cm, 0, OFF_CD4);

    zero_pad_kernel<<<(BROWS + 255) / 256, 256>>>(Cm);
    pack_b_kernel<<<dim3(NOUT / (256 * 8), KPAD), 256>>>(b0, b1, b2, b3, b4, Bm);

    gemm_kernel<<<dim3(NOUT / BN, BROWS / BM), 256, SMEM_BYTES>>>(Cm, Bm, out);
}

// round 8
// speedup vs baseline: 1.4850x; 1.1612x over previous
#include <cuda_runtime.h>
#include <cuda_fp16.h>
#include <cstdint>

// ---------------- problem constants ----------------
#define BROWS 4096
#define NOUT  4096
#define KTOT  4122
#define KPAD  4160            // 65 * 64

#define OFF_CD4 262
#define OFF_CD3 524
#define OFF_CD2 1042
#define OFF_CD1 2071

// ---------------- scratch (device globals; no allocs allowed) ----------------
__device__ __half g_C[(size_t)BROWS * KPAD];   // coeffs [M, K] row-major fp16
__device__ __half g_B[(size_t)KPAD * NOUT];    // stacked bases [K, N] row-major fp16

__constant__ float c_lo[8] = {
    -0.010597401784997278f,  0.032883011666982945f,  0.030841381835986965f,
    -0.18703481171888114f,  -0.02798376941698385f,   0.6308807679295904f,
     0.7148465705525415f,    0.23037781330885523f };
__constant__ float c_hi[8] = {
    -0.23037781330885523f,   0.7148465705525415f,   -0.6308807679295904f,
    -0.02798376941698385f,   0.18703481171888114f,   0.030841381835986965f,
    -0.032883011666982945f, -0.010597401784997278f };

// ---------------- fused DWT: all 4 db4 levels for one row, in smem ----------------
// pywt 'symmetric': out[j] = sum_m filt[m] * E[8+2j-m],
// E[i] = a[6-i] (i<7), a[i-7] (i<Nin+7), a[2*Nin+6-i] otherwise.
__global__ void __launch_bounds__(256)
dwt_fused_kernel(const float* __restrict__ x, __half* __restrict__ C)
{
    __shared__ float bufA[4096];
    __shared__ float bufB[2051];

    const int row = blockIdx.x;
    const int tid = threadIdx.x;
    const float* xr = x + (size_t)row * 4096;
    __half* Crow = C + (size_t)row * KPAD;

    // load row (coalesced float4)
    const float4* x4 = (const float4*)xr;
    float4* bA4 = (float4*)bufA;
#pragma unroll
    for (int i = 0; i < 4; i++) bA4[tid + i * 256] = x4[tid + i * 256];

    // zero padding cols KTOT..KPAD
    for (int c = KTOT + tid; c < KPAD; c += 256) Crow[c] = __float2half_rn(0.f);
    __syncthreads();

    const int nin[4]  = {4096, 2051, 1029, 518};
    const int nout[4] = {2051, 1029, 518, 262};
    const int offD[4] = {OFF_CD1, OFF_CD2, OFF_CD3, OFF_CD4};

    float* src = bufA;
    float* dst = bufB;
#pragma unroll 1
    for (int lv = 0; lv < 4; lv++) {
        const int Nin = nin[lv], Nout = nout[lv];
        for (int j = tid; j < Nout; j += 256) {
            float sLo = 0.f, sHi = 0.f;
#pragma unroll
            for (int m = 0; m < 8; m++) {
                const int i = 8 + 2 * j - m;
                int idx;
                if (i < 7)            idx = 6 - i;
                else if (i < Nin + 7) idx = i - 7;
                else                  idx = 2 * Nin + 6 - i;
                const float v = src[idx];
                sLo = fmaf(c_lo[m], v, sLo);
                sHi = fmaf(c_hi[m], v, sHi);
            }
            Crow[offD[lv] + j] = __float2half_rn(sHi);
            if (lv < 3) dst[j] = sLo;
            else        Crow[j] = __float2half_rn(sLo);   // cA4 at col 0
        }
        __syncthreads();
        float* tmp = src; src = dst; dst = tmp;
    }
}

// ---------------- pack bases -> fp16 stacked [KPAD, 4096] row-major ----------------
__global__ void pack_b_kernel(const float* __restrict__ b0, const float* __restrict__ b1,
                              const float* __restrict__ b2, const float* __restrict__ b3,
                              const float* __restrict__ b4, __half* __restrict__ Bh)
{
    int n = (blockIdx.x * blockDim.x + threadIdx.x) * 8;
    int k = blockIdx.y;
    if (n >= NOUT) return;

    const float* src = nullptr; int r = 0;
    if      (k < OFF_CD4) { src = b0; r = k; }
    else if (k < OFF_CD3) { src = b1; r = k - OFF_CD4; }
    else if (k < OFF_CD2) { src = b2; r = k - OFF_CD3; }
    else if (k < OFF_CD1) { src = b3; r = k - OFF_CD2; }
    else if (k < KTOT)    { src = b4; r = k - OFF_CD1; }

    __half2 h[4];
    if (src) {
        const float4* p = (const float4*)(src + (size_t)r * NOUT + n);
        float4 v0 = p[0], v1 = p[1];
        h[0] = __floats2half2_rn(v0.x, v0.y);
        h[1] = __floats2half2_rn(v0.z, v0.w);
        h[2] = __floats2half2_rn(v1.x, v1.y);
        h[3] = __floats2half2_rn(v1.z, v1.w);
    } else {
        h[0] = h[1] = h[2] = h[3] = __half2half2(__float2half_rn(0.f));
    }
    *(int4*)(Bh + (size_t)k * NOUT + n) = *(int4*)h;
}

// ---------------- GEMM: [4096,4160] x [4160,4096] fp16 -> fp32 ----------------
// mma.sync.m16n8k16 + ldmatrix + 3-stage cp.async, BK=64, 2 CTAs/SM.
// CTA tile 128x128, 256 threads, 8 warps as 2(m) x 4(n), warp tile 64x32.
#define BM 128
#define BN 128
#define BK 64
#define STAGES 3
#define A_STAGE_BYTES 16384     // 128 rows x 64 halves (128B rows)
#define B_STAGE_BYTES 16384     // 64 rows x 128 halves (256B rows)
#define STAGE_BYTES   32768
#define SMEM_BYTES    (STAGES * STAGE_BYTES)   // 98304

// A smem: 128B rows, 8 chunks of 16B; chunk ^= (row & 7)
__device__ __forceinline__ uint32_t aswz(int r, int chunk) {
    return (uint32_t)(r * 128 + ((chunk ^ (r & 7)) << 4));
}
// B smem: 256B rows, 16 chunks of 16B; low-3 chunk bits ^= (row & 7)
__device__ __forceinline__ uint32_t bswz(int r, int chunk) {
    return (uint32_t)(r * 256 + (((chunk & 8) | ((chunk ^ r) & 7)) << 4));
}

__device__ __forceinline__ void cp16(uint32_t saddr, const void* gaddr) {
    asm volatile("cp.async.cg.shared.global [%0], [%1], 16;\n" :: "r"(saddr), "l"(gaddr));
}
__device__ __forceinline__ void ldsm4(uint32_t* r, uint32_t addr) {
    asm volatile("ldmatrix.sync.aligned.m8n8.x4.shared.b16 {%0,%1,%2,%3}, [%4];"
                 : "=r"(r[0]), "=r"(r[1]), "=r"(r[2]), "=r"(r[3]) : "r"(addr));
}
__device__ __forceinline__ void ldsm4t(uint32_t* r, uint32_t addr) {
    asm volatile("ldmatrix.sync.aligned.m8n8.x4.trans.shared.b16 {%0,%1,%2,%3}, [%4];"
                 : "=r"(r[0]), "=r"(r[1]), "=r"(r[2]), "=r"(r[3]) : "r"(addr));
}
__device__ __forceinline__ void mma16816(float* c, const uint32_t* a, uint32_t b0, uint32_t b1) {
    asm volatile("mma.sync.aligned.m16n8k16.row.col.f32.f16.f16.f32 "
                 "{%0,%1,%2,%3}, {%4,%5,%6,%7}, {%8,%9}, {%0,%1,%2,%3};"
                 : "+f"(c[0]), "+f"(c[1]), "+f"(c[2]), "+f"(c[3])
                 : "r"(a[0]), "r"(a[1]), "r"(a[2]), "r"(a[3]), "r"(b0), "r"(b1));
}

__global__ void __launch_bounds__(256, 2)
gemm_kernel(const __half* __restrict__ A, const __half* __restrict__ Bm,
            float* __restrict__ Cout)
{
    constexpr int K = KPAD, N = NOUT;
    extern __shared__ char smem[];
    const uint32_t sbase = (uint32_t)__cvta_generic_to_shared(smem);

    const int tid = threadIdx.x;
    const int wid = tid >> 5, lid = tid & 31;
    const int wm  = wid & 1;        // 0..1 -> 64-row slice
    const int wn  = wid >> 1;       // 0..3 -> 32-col slice
    const int rowBase = blockIdx.y * BM;
    const int colBase = blockIdx.x * BN;

    const int l15 = lid & 15, lc = lid >> 4;

    // ---- loader geometry ----
    int aR[4]; uint32_t aS[4];
#pragma unroll
    for (int i = 0; i < 4; i++) {
        const int idx = i * 256 + tid;
        aR[i] = idx >> 3;
        aS[i] = aswz(aR[i], idx & 7);
    }
    int bR[4]; uint32_t bS[4];
#pragma unroll
    for (int i = 0; i < 4; i++) {
        const int idx = i * 256 + tid;
        bR[i] = idx >> 4;
        bS[i] = bswz(bR[i], idx & 15);
    }

    const __half* Ag = A + (size_t)rowBase * K;
    const __half* Bg = Bm + colBase;

    // ---- ldmatrix bases ----
    uint32_t aBase[4]; int aX[4];
#pragma unroll
    for (int i = 0; i < 4; i++) {
        const int r = wm * 64 + i * 16 + l15;
        aBase[i] = (uint32_t)(r * 128);
        aX[i] = r & 7;
    }
    int bChunk[2] = { wn * 4 + 0 * 2 + lc, wn * 4 + 1 * 2 + lc };

    auto issue_stage = [&](int t, int slot) {
        const int kb = t * BK;
        const uint32_t sa = sbase + slot * STAGE_BYTES;
        const uint32_t sb = sa + A_STAGE_BYTES;
#pragma unroll
        for (int i = 0; i < 4; i++) {
            const int idx = i * 256 + tid;
            cp16(sa + aS[i], Ag + (size_t)aR[i] * K + kb + (idx & 7) * 8);
        }
#pragma unroll
        for (int i = 0; i < 4; i++) {
            const int idx = i * 256 + tid;
            cp16(sb + bS[i], Bg + (size_t)(kb + bR[i]) * N + (idx & 15) * 8);
        }
        asm volatile("cp.async.commit_group;\n" ::: "memory");
    };

    float acc[4][4][4];
#pragma unroll
    for (int i = 0; i < 4; i++)
#pragma unroll
        for (int j = 0; j < 4; j++)
#pragma unroll
            for (int q = 0; q < 4; q++) acc[i][j][q] = 0.f;

    constexpr int NT = K / BK;    // 65
    issue_stage(0, 0);
    issue_stage(1, 1);

    int cs = 0, ps = 2;
    for (int t = 0; t < NT; t++) {
        asm volatile("cp.async.wait_group 1;\n" ::: "memory");
        __syncthreads();
        if (t + 2 < NT) issue_stage(t + 2, ps);

        const uint32_t sa = sbase + cs * STAGE_BYTES;
        const uint32_t sb = sa + A_STAGE_BYTES;

#pragma unroll
        for (int ks = 0; ks < 4; ks++) {
            uint32_t af[4][4], bf[2][4];
#pragma unroll
            for (int i = 0; i < 4; i++)
                ldsm4(af[i], sa + aBase[i] + (uint32_t)((((ks * 2 + lc) ^ aX[i]) << 4)));
#pragma unroll
            for (int g = 0; g < 2; g++) {
                const int r = ks * 16 + l15;
                ldsm4t(bf[g], sb + (uint32_t)(r * 256 +
                        (((bChunk[g] & 8) | ((bChunk[g] ^ r) & 7)) << 4)));
            }
#pragma unroll
            for (int i = 0; i < 4; i++)
#pragma unroll
                for (int j = 0; j < 4; j++)
                    mma16816(acc[i][j], af[i], bf[j >> 1][(j & 1) * 2],
                             bf[j >> 1][(j & 1) * 2 + 1]);
        }
        cs = (cs == STAGES - 1) ? 0 : cs + 1;
        ps = (ps == STAGES - 1) ? 0 : ps + 1;
    }

    // ---- epilogue: fragment -> gmem, streaming stores (keep A/B in L2) ----
    const int er = lid >> 2, ec = (lid & 3) * 2;
#pragma unroll
    for (int i = 0; i < 4; i++) {
        const int row0 = rowBase + wm * 64 + i * 16 + er;
#pragma unroll
        for (int j = 0; j < 4; j++) {
            const int col = colBase + wn * 32 + j * 8 + ec;
            float2* p0 = (float2*)(Cout + (size_t)row0 * N + col);
            float2* p1 = (float2*)(Cout + (size_t)(row0 + 8) * N + col);
            __stcs(p0, make_float2(acc[i][j][0], acc[i][j][1]));
            __stcs(p1, make_float2(acc[i][j][2], acc[i][j][3]));
        }
    }
}

// ---------------- launch ----------------
extern "C" void kernel_launch(void* const* d_in, const int* in_sizes, int n_in,
                              void* d_out, int out_size)
{
    const float* x  = (const float*)d_in[0];
    const float* b0 = (const float*)d_in[1];
    const float* b1 = (const float*)d_in[2];
    const float* b2 = (const float*)d_in[3];
    const float* b3 = (const float*)d_in[4];
    const float* b4 = (const float*)d_in[5];
    float* out = (float*)d_out;

    __half *Cm, *Bm;
    cudaGetSymbolAddress((void**)&Cm, g_C);
    cudaGetSymbolAddress((void**)&Bm, g_B);

    cudaFuncSetAttribute(gemm_kernel,
                         cudaFuncAttributeMaxDynamicSharedMemorySize, SMEM_BYTES);

    dwt_fused_kernel<<<BROWS, 256>>>(x, Cm);
    pack_b_kernel<<<dim3(NOUT / (256 * 8), KPAD), 256>>>(b0, b1, b2, b3, b4, Bm);
    gemm_kernel<<<dim3(NOUT / BN, BROWS / BM), 256, SMEM_BYTES>>>(Cm, Bm, out);
}

// round 9
// speedup vs baseline: 1.5449x; 1.0403x over previous
#include <cuda_runtime.h>
#include <cuda_fp16.h>
#include <cstdint>

// ---------------- problem constants ----------------
#define BROWS 4096
#define NOUT  4096
#define KTOT  4122
#define KPAD  4160            // 65 * 64

#define OFF_CD4 262
#define OFF_CD3 524
#define OFF_CD2 1042
#define OFF_CD1 2071

// ---------------- scratch (device globals; no allocs allowed) ----------------
__device__ __half g_C[(size_t)BROWS * KPAD];   // coeffs [M, K] row-major fp16
__device__ __half g_B[(size_t)KPAD * NOUT];    // stacked bases [K, N] row-major fp16

__constant__ float c_lo[8] = {
    -0.010597401784997278f,  0.032883011666982945f,  0.030841381835986965f,
    -0.18703481171888114f,  -0.02798376941698385f,   0.6308807679295904f,
     0.7148465705525415f,    0.23037781330885523f };
__constant__ float c_hi[8] = {
    -0.23037781330885523f,   0.7148465705525415f,   -0.6308807679295904f,
    -0.02798376941698385f,   0.18703481171888114f,   0.030841381835986965f,
    -0.032883011666982945f, -0.010597401784997278f };

// ---------------- fused DWT: all 4 db4 levels for one row, in smem ----------------
// pywt 'symmetric': out[j] = sum_m filt[m] * E[8+2j-m],
// E[i] = a[6-i] (i<7), a[i-7] (i<Nin+7), a[2*Nin+6-i] otherwise.
// Interior fast path (j>=4 && 2j <= Nin-2): E[8+2j-m] = a[2j+1-m], contiguous window.
__global__ void __launch_bounds__(256)
dwt_fused_kernel(const float* __restrict__ x, __half* __restrict__ C)
{
    __shared__ float bufA[4096];
    __shared__ float bufB[2051];

    const int row = blockIdx.x;
    const int tid = threadIdx.x;
    const float* xr = x + (size_t)row * 4096;
    __half* Crow = C + (size_t)row * KPAD;

    // load row (coalesced float4)
    const float4* x4 = (const float4*)xr;
    float4* bA4 = (float4*)bufA;
#pragma unroll
    for (int i = 0; i < 4; i++) bA4[tid + i * 256] = x4[tid + i * 256];

    // zero padding cols KTOT..KPAD
    for (int c = KTOT + tid; c < KPAD; c += 256) Crow[c] = __float2half_rn(0.f);
    __syncthreads();

    const int nin[4]  = {4096, 2051, 1029, 518};
    const int nout[4] = {2051, 1029, 518, 262};
    const int offD[4] = {OFF_CD1, OFF_CD2, OFF_CD3, OFF_CD4};

    float* src = bufA;
    float* dst = bufB;
#pragma unroll 1
    for (int lv = 0; lv < 4; lv++) {
        const int Nin = nin[lv], Nout = nout[lv];
        const int jIntHi = (Nin - 2) >> 1;          // last interior j
        for (int j = tid; j < Nout; j += 256) {
            float sLo = 0.f, sHi = 0.f;
            if (j >= 4 && j <= jIntHi) {
                // interior: contiguous window, same accumulation order as reference
                const float* p = src + 2 * j - 6;   // p[7-m] = a[2j+1-m]
#pragma unroll
                for (int m = 0; m < 8; m++) {
                    const float v = p[7 - m];
                    sLo = fmaf(c_lo[m], v, sLo);
                    sHi = fmaf(c_hi[m], v, sHi);
                }
            } else {
#pragma unroll
                for (int m = 0; m < 8; m++) {
                    const int i = 8 + 2 * j - m;
                    int idx;
                    if (i < 7)            idx = 6 - i;
                    else if (i < Nin + 7) idx = i - 7;
                    else                  idx = 2 * Nin + 6 - i;
                    const float v = src[idx];
                    sLo = fmaf(c_lo[m], v, sLo);
                    sHi = fmaf(c_hi[m], v, sHi);
                }
            }
            Crow[offD[lv] + j] = __float2half_rn(sHi);
            if (lv < 3) dst[j] = sLo;
            else        Crow[j] = __float2half_rn(sLo);   // cA4 at col 0
        }
        __syncthreads();
        float* tmp = src; src = dst; dst = tmp;
    }
}

// ---------------- pack bases -> fp16 stacked [KPAD, 4096] row-major ----------------
__global__ void pack_b_kernel(const float* __restrict__ b0, const float* __restrict__ b1,
                              const float* __restrict__ b2, const float* __restrict__ b3,
                              const float* __restrict__ b4, __half* __restrict__ Bh)
{
    int n = (blockIdx.x * blockDim.x + threadIdx.x) * 8;
    int k = blockIdx.y;
    if (n >= NOUT) return;

    const float* src = nullptr; int r = 0;
    if      (k < OFF_CD4) { src = b0; r = k; }
    else if (k < OFF_CD3) { src = b1; r = k - OFF_CD4; }
    else if (k < OFF_CD2) { src = b2; r = k - OFF_CD3; }
    else if (k < OFF_CD1) { src = b3; r = k - OFF_CD2; }
    else if (k < KTOT)    { src = b4; r = k - OFF_CD1; }

    __half2 h[4];
    if (src) {
        const float4* p = (const float4*)(src + (size_t)r * NOUT + n);
        float4 v0 = p[0], v1 = p[1];
        h[0] = __floats2half2_rn(v0.x, v0.y);
        h[1] = __floats2half2_rn(v0.z, v0.w);
        h[2] = __floats2half2_rn(v1.x, v1.y);
        h[3] = __floats2half2_rn(v1.z, v1.w);
    } else {
        h[0] = h[1] = h[2] = h[3] = __half2half2(__float2half_rn(0.f));
    }
    *(int4*)(Bh + (size_t)k * NOUT + n) = *(int4*)h;
}

// ---------------- GEMM: [4096,4160] x [4160,4096] fp16 -> fp32 ----------------
// mma.sync.m16n8k16 + ldmatrix + 3-stage cp.async, BK=64, 2 CTAs/SM.
// CTA tile 128x128, 256 threads, 8 warps as 2(m) x 4(n), warp tile 64x32.
#define BM 128
#define BN 128
#define BK 64
#define STAGES 3
#define A_STAGE_BYTES 16384     // 128 rows x 64 halves (128B rows)
#define B_STAGE_BYTES 16384     // 64 rows x 128 halves (256B rows)
#define STAGE_BYTES   32768
#define SMEM_BYTES    (STAGES * STAGE_BYTES)   // 98304

// A smem: 128B rows, 8 chunks of 16B; chunk ^= (row & 7)
__device__ __forceinline__ uint32_t aswz(int r, int chunk) {
    return (uint32_t)(r * 128 + ((chunk ^ (r & 7)) << 4));
}
// B smem: 256B rows, 16 chunks of 16B; low-3 chunk bits ^= (row & 7)
__device__ __forceinline__ uint32_t bswz(int r, int chunk) {
    return (uint32_t)(r * 256 + (((chunk & 8) | ((chunk ^ r) & 7)) << 4));
}

__device__ __forceinline__ void cp16(uint32_t saddr, const void* gaddr) {
    asm volatile("cp.async.cg.shared.global [%0], [%1], 16;\n" :: "r"(saddr), "l"(gaddr));
}
__device__ __forceinline__ void ldsm4(uint32_t* r, uint32_t addr) {
    asm volatile("ldmatrix.sync.aligned.m8n8.x4.shared.b16 {%0,%1,%2,%3}, [%4];"
                 : "=r"(r[0]), "=r"(r[1]), "=r"(r[2]), "=r"(r[3]) : "r"(addr));
}
__device__ __forceinline__ void ldsm4t(uint32_t* r, uint32_t addr) {
    asm volatile("ldmatrix.sync.aligned.m8n8.x4.trans.shared.b16 {%0,%1,%2,%3}, [%4];"
                 : "=r"(r[0]), "=r"(r[1]), "=r"(r[2]), "=r"(r[3]) : "r"(addr));
}
__device__ __forceinline__ void mma16816(float* c, const uint32_t* a, uint32_t b0, uint32_t b1) {
    asm volatile("mma.sync.aligned.m16n8k16.row.col.f32.f16.f16.f32 "
                 "{%0,%1,%2,%3}, {%4,%5,%6,%7}, {%8,%9}, {%0,%1,%2,%3};"
                 : "+f"(c[0]), "+f"(c[1]), "+f"(c[2]), "+f"(c[3])
                 : "r"(a[0]), "r"(a[1]), "r"(a[2]), "r"(a[3]), "r"(b0), "r"(b1));
}

__global__ void __launch_bounds__(256, 2)
gemm_kernel(const __half* __restrict__ A, const __half* __restrict__ Bm,
            float* __restrict__ Cout)
{
    constexpr int K = KPAD, N = NOUT;
    extern __shared__ char smem[];
    const uint32_t sbase = (uint32_t)__cvta_generic_to_shared(smem);

    const int tid = threadIdx.x;
    const int wid = tid >> 5, lid = tid & 31;
    const int wm  = wid & 1;        // 0..1 -> 64-row slice
    const int wn  = wid >> 1;       // 0..3 -> 32-col slice
    const int rowBase = blockIdx.y * BM;
    const int colBase = blockIdx.x * BN;

    const int l15 = lid & 15, lc = lid >> 4;

    // ---- loader geometry ----
    int aR[4]; uint32_t aS[4];
#pragma unroll
    for (int i = 0; i < 4; i++) {
        const int idx = i * 256 + tid;
        aR[i] = idx >> 3;
        aS[i] = aswz(aR[i], idx & 7);
    }
    int bR[4]; uint32_t bS[4];
#pragma unroll
    for (int i = 0; i < 4; i++) {
        const int idx = i * 256 + tid;
        bR[i] = idx >> 4;
        bS[i] = bswz(bR[i], idx & 15);
    }

    const __half* Ag = A + (size_t)rowBase * K;
    const __half* Bg = Bm + colBase;

    // ---- ldmatrix bases ----
    uint32_t aBase[4]; int aX[4];
#pragma unroll
    for (int i = 0; i < 4; i++) {
        const int r = wm * 64 + i * 16 + l15;
        aBase[i] = (uint32_t)(r * 128);
        aX[i] = r & 7;
    }
    int bChunk[2] = { wn * 4 + 0 * 2 + lc, wn * 4 + 1 * 2 + lc };

    auto issue_stage = [&](int t, int slot) {
        const int kb = t * BK;
        const uint32_t sa = sbase + slot * STAGE_BYTES;
        const uint32_t sb = sa + A_STAGE_BYTES;
#pragma unroll
        for (int i = 0; i < 4; i++) {
            const int idx = i * 256 + tid;
            cp16(sa + aS[i], Ag + (size_t)aR[i] * K + kb + (idx & 7) * 8);
        }
#pragma unroll
        for (int i = 0; i < 4; i++) {
            const int idx = i * 256 + tid;
            cp16(sb + bS[i], Bg + (size_t)(kb + bR[i]) * N + (idx & 15) * 8);
        }
        asm volatile("cp.async.commit_group;\n" ::: "memory");
    };

    float acc[4][4][4];
#pragma unroll
    for (int i = 0; i < 4; i++)
#pragma unroll
        for (int j = 0; j < 4; j++)
#pragma unroll
            for (int q = 0; q < 4; q++) acc[i][j][q] = 0.f;

    constexpr int NT = K / BK;    // 65
    issue_stage(0, 0);
    issue_stage(1, 1);

    int cs = 0, ps = 2;
    for (int t = 0; t < NT; t++) {
        asm volatile("cp.async.wait_group 1;\n" ::: "memory");
        __syncthreads();
        if (t + 2 < NT) issue_stage(t + 2, ps);

        const uint32_t sa = sbase + cs * STAGE_BYTES;
        const uint32_t sb = sa + A_STAGE_BYTES;

#pragma unroll
        for (int ks = 0; ks < 4; ks++) {
            uint32_t af[4][4], bf[2][4];
#pragma unroll
            for (int i = 0; i < 4; i++)
                ldsm4(af[i], sa + aBase[i] + (uint32_t)((((ks * 2 + lc) ^ aX[i]) << 4)));
#pragma unroll
            for (int g = 0; g < 2; g++) {
                const int r = ks * 16 + l15;
                ldsm4t(bf[g], sb + (uint32_t)(r * 256 +
                        (((bChunk[g] & 8) | ((bChunk[g] ^ r) & 7)) << 4)));
            }
#pragma unroll
            for (int i = 0; i < 4; i++)
#pragma unroll
                for (int j = 0; j < 4; j++)
                    mma16816(acc[i][j], af[i], bf[j >> 1][(j & 1) * 2],
                             bf[j >> 1][(j & 1) * 2 + 1]);
        }
        cs = (cs == STAGES - 1) ? 0 : cs + 1;
        ps = (ps == STAGES - 1) ? 0 : ps + 1;
    }

    // ---- epilogue: fragment -> gmem, streaming stores (keep A/B in L2) ----
    const int er = lid >> 2, ec = (lid & 3) * 2;
#pragma unroll
    for (int i = 0; i < 4; i++) {
        const int row0 = rowBase + wm * 64 + i * 16 + er;
#pragma unroll
        for (int j = 0; j < 4; j++) {
            const int col = colBase + wn * 32 + j * 8 + ec;
            float2* p0 = (float2*)(Cout + (size_t)row0 * N + col);
            float2* p1 = (float2*)(Cout + (size_t)(row0 + 8) * N + col);
            __stcs(p0, make_float2(acc[i][j][0], acc[i][j][1]));
            __stcs(p1, make_float2(acc[i][j][2], acc[i][j][3]));
        }
    }
}

// ---------------- launch ----------------
extern "C" void kernel_launch(void* const* d_in, const int* in_sizes, int n_in,
                              void* d_out, int out_size)
{
    const float* x  = (const float*)d_in[0];
    const float* b0 = (const float*)d_in[1];
    const float* b1 = (const float*)d_in[2];
    const float* b2 = (const float*)d_in[3];
    const float* b3 = (const float*)d_in[4];
    const float* b4 = (const float*)d_in[5];
    float* out = (float*)d_out;

    __half *Cm, *Bm;
    cudaGetSymbolAddress((void**)&Cm, g_C);
    cudaGetSymbolAddress((void**)&Bm, g_B);

    cudaFuncSetAttribute(gemm_kernel,
                         cudaFuncAttributeMaxDynamicSharedMemorySize, SMEM_BYTES);

    dwt_fused_kernel<<<BROWS, 256>>>(x, Cm);
    pack_b_kernel<<<dim3(NOUT / (256 * 8), KPAD), 256>>>(b0, b1, b2, b3, b4, Bm);
    gemm_kernel<<<dim3(NOUT / BN, BROWS / BM), 256, SMEM_BYTES>>>(Cm, Bm, out);
}